// round 1
// baseline (speedup 1.0000x reference)
#include <cuda_runtime.h>
#include <math.h>

// ---------------- problem constants ----------------
#define BB   4
#define PP   2048
#define DD   1024
#define HH   16
#define KVH  8
#define HDIM 64
#define FFN  4096
#define NE   16
#define FE   256
#define NTOK (BB*PP)          // 8192

// ---------------- scratch (no allocs allowed) ----------------
__device__ float g_h   [(size_t)NTOK*DD];
__device__ float g_q   [(size_t)NTOK*HH*HDIM];
__device__ float g_k   [(size_t)NTOK*KVH*HDIM];
__device__ float g_v   [(size_t)NTOK*KVH*HDIM];
__device__ float g_att [(size_t)NTOK*DD];
__device__ float g_x2  [(size_t)NTOK*DD];
__device__ float g_h2  [(size_t)NTOK*DD];
__device__ float g_gate[(size_t)NTOK*FFN];
__device__ float g_up  [(size_t)NTOK*FFN];
__device__ float g_eg  [(size_t)NTOK*NE*FE];
__device__ float g_eu  [(size_t)NTOK*NE*FE];
__device__ float g_tmp [(size_t)NTOK*DD];

// ---------------- RMSNorm: one block per row, D=1024 = 256 thr * float4 ----------------
__global__ void rmsnorm_kernel(const float* __restrict__ x, const float* __restrict__ w,
                               float* __restrict__ out)
{
    int row = blockIdx.x;
    int tid = threadIdx.x;
    const float4 v = ((const float4*)(x + (size_t)row*DD))[tid];
    float ss = v.x*v.x + v.y*v.y + v.z*v.z + v.w*v.w;
    #pragma unroll
    for (int o = 16; o; o >>= 1) ss += __shfl_xor_sync(0xffffffffu, ss, o);
    __shared__ float red[8];
    if ((tid & 31) == 0) red[tid >> 5] = ss;
    __syncthreads();
    float total = red[0]+red[1]+red[2]+red[3]+red[4]+red[5]+red[6]+red[7];
    float sc = rsqrtf(total * (1.0f/DD) + 1e-6f);
    const float4 wv = ((const float4*)w)[tid];
    float4 o4;
    o4.x = v.x*sc*wv.x; o4.y = v.y*sc*wv.y; o4.z = v.z*sc*wv.z; o4.w = v.w*sc*wv.w;
    ((float4*)(out + (size_t)row*DD))[tid] = o4;
}

// ---------------- RoPE (in place), pairs (i, i+32) per head ----------------
__global__ void rope_kernel(float* __restrict__ buf, int nheads, long total)
{
    long idx = (long)blockIdx.x * blockDim.x + threadIdx.x;
    if (idx >= total) return;
    int  i    = (int)(idx & 31);
    int  head = (int)((idx >> 5) % nheads);
    long t    = idx / (32L * nheads);
    int  p    = (int)(t % PP);
    float inv = powf(10000.0f, -(float)i * (1.0f/32.0f));
    float ang = (float)p * inv;
    float c = cosf(ang), s = sinf(ang);
    float* v = buf + t * ((size_t)nheads * HDIM) + (size_t)head * HDIM + i;
    float a = v[0], b = v[32];
    v[0]  = a*c - b*s;
    v[32] = b*c + a*s;
}

// ---------------- generic fp32 SGEMM: 128x128x8, 8x8/thread ----------------
// C[M x N] (+z*sC) = A[M x K] @ (B + z*sB)[K x N]   (ldb == N)
// EPI: 0 = none, 1 = +bias[col], 2 = +res[r*ldc + c]
template<int EPI>
__global__ __launch_bounds__(256, 2)
void sgemm_kernel(const float* __restrict__ A, const float* __restrict__ B,
                  float* __restrict__ C, int M, int N, int K, int ldc,
                  const float* __restrict__ bias, const float* __restrict__ res,
                  long sB, long sC)
{
    B += (long)blockIdx.z * sB;
    C += (long)blockIdx.z * sC;
    const int bm = blockIdx.y * 128, bn = blockIdx.x * 128;

    __shared__ __align__(16) float As[8][132];
    __shared__ __align__(16) float Bs[8][132];

    const int tid = threadIdx.x;
    const int tx  = tid & 15, ty = tid >> 4;
    const int la_r = tid >> 1,  la_c = (tid & 1)  * 4;
    const int lb_r = tid >> 5,  lb_c = (tid & 31) * 4;

    const float* Ap = A + (size_t)(bm + la_r) * K + la_c;
    const float* Bp = B + (size_t)lb_r * N + bn + lb_c;

    float acc[8][8];
    #pragma unroll
    for (int i = 0; i < 8; i++)
        #pragma unroll
        for (int j = 0; j < 8; j++) acc[i][j] = 0.0f;

    for (int k0 = 0; k0 < K; k0 += 8) {
        float4 a = *(const float4*)(Ap + k0);
        float4 b = *(const float4*)(Bp + (size_t)k0 * N);
        As[la_c+0][la_r] = a.x; As[la_c+1][la_r] = a.y;
        As[la_c+2][la_r] = a.z; As[la_c+3][la_r] = a.w;
        *(float4*)&Bs[lb_r][lb_c] = b;
        __syncthreads();
        #pragma unroll
        for (int kk = 0; kk < 8; kk++) {
            float4 a0 = *(const float4*)&As[kk][ty*4];
            float4 a1 = *(const float4*)&As[kk][64 + ty*4];
            float4 b0 = *(const float4*)&Bs[kk][tx*4];
            float4 b1 = *(const float4*)&Bs[kk][64 + tx*4];
            float ar[8] = {a0.x,a0.y,a0.z,a0.w,a1.x,a1.y,a1.z,a1.w};
            float br[8] = {b0.x,b0.y,b0.z,b0.w,b1.x,b1.y,b1.z,b1.w};
            #pragma unroll
            for (int i = 0; i < 8; i++)
                #pragma unroll
                for (int j = 0; j < 8; j++)
                    acc[i][j] += ar[i] * br[j];
        }
        __syncthreads();
    }

    #pragma unroll
    for (int i = 0; i < 8; i++) {
        int r = bm + ((i < 4) ? (ty*4 + i) : (64 + ty*4 + i - 4));
        #pragma unroll
        for (int jh = 0; jh < 2; jh++) {
            int c = bn + jh*64 + tx*4;
            float4 o;
            o.x = acc[i][jh*4+0]; o.y = acc[i][jh*4+1];
            o.z = acc[i][jh*4+2]; o.w = acc[i][jh*4+3];
            if (EPI == 1) {
                o.x += bias[c+0]; o.y += bias[c+1]; o.z += bias[c+2]; o.w += bias[c+3];
            }
            if (EPI == 2) {
                float4 rv = *(const float4*)(res + (size_t)r * ldc + c);
                o.x += rv.x; o.y += rv.y; o.z += rv.z; o.w += rv.w;
            }
            *(float4*)(C + (size_t)r * ldc + c) = o;
        }
    }
}

// ---------------- causal flash attention, fp32, 64x64 tiles, HD=64 ----------------
// grid: (P/64, H, B); block 256 threads; dyn smem = 4 * 64*68 * 4 bytes
__global__ __launch_bounds__(256, 2)
void flash_kernel(const float* __restrict__ q, const float* __restrict__ k,
                  const float* __restrict__ v, float* __restrict__ out)
{
    extern __shared__ float sm[];
    float* qs = sm;               // [hd][row]  stride 68
    float* ks = sm + 64*68;       // [hd][col]
    float* vs = sm + 2*64*68;     // [kk][hd]
    float* ps = sm + 3*64*68;     // [kcol][row]

    const int b = blockIdx.z, h = blockIdx.y, qt = blockIdx.x;
    const int q0 = qt * 64;
    const float* qb = q + (size_t)b*PP*(HH*HDIM)  + (size_t)h*HDIM;
    const float* kb = k + (size_t)b*PP*(KVH*HDIM) + (size_t)(h>>1)*HDIM;
    const float* vb = v + (size_t)b*PP*(KVH*HDIM) + (size_t)(h>>1)*HDIM;

    const int tid = threadIdx.x;
    const int tx = tid & 15, ty = tid >> 4;
    const int lr = tid >> 4, lc = (tid & 15) * 4;

    // load Q tile, transposed + pre-scaled by 1/sqrt(HD)
    for (int rr = lr; rr < 64; rr += 16) {
        float4 a = *(const float4*)(qb + (size_t)(q0+rr)*(HH*HDIM) + lc);
        qs[(lc+0)*68+rr] = a.x*0.125f; qs[(lc+1)*68+rr] = a.y*0.125f;
        qs[(lc+2)*68+rr] = a.z*0.125f; qs[(lc+3)*68+rr] = a.w*0.125f;
    }

    float m_i[4], l_i[4], o[4][4];
    #pragma unroll
    for (int i = 0; i < 4; i++) {
        m_i[i] = -1e30f; l_i[i] = 0.0f;
        o[i][0]=o[i][1]=o[i][2]=o[i][3]=0.0f;
    }

    for (int t = 0; t <= qt; t++) {
        const int k0 = t * 64;
        __syncthreads();
        // load K (transposed) and V (natural)
        for (int rr = lr; rr < 64; rr += 16) {
            float4 a = *(const float4*)(kb + (size_t)(k0+rr)*(KVH*HDIM) + lc);
            ks[(lc+0)*68+rr] = a.x; ks[(lc+1)*68+rr] = a.y;
            ks[(lc+2)*68+rr] = a.z; ks[(lc+3)*68+rr] = a.w;
            float4 w4 = *(const float4*)(vb + (size_t)(k0+rr)*(KVH*HDIM) + lc);
            *(float4*)(vs + rr*68 + lc) = w4;
        }
        __syncthreads();

        // S = Q @ K^T
        float s[4][4] = {{0,0,0,0},{0,0,0,0},{0,0,0,0},{0,0,0,0}};
        #pragma unroll 4
        for (int kk = 0; kk < 64; kk++) {
            float4 qa = *(const float4*)(qs + kk*68 + ty*4);
            float4 ka = *(const float4*)(ks + kk*68 + tx*4);
            float qr[4] = {qa.x,qa.y,qa.z,qa.w};
            float kr[4] = {ka.x,ka.y,ka.z,ka.w};
            #pragma unroll
            for (int i = 0; i < 4; i++)
                #pragma unroll
                for (int j = 0; j < 4; j++)
                    s[i][j] += qr[i]*kr[j];
        }

        if (t == qt) {   // diagonal tile: causal mask
            #pragma unroll
            for (int i = 0; i < 4; i++)
                #pragma unroll
                for (int j = 0; j < 4; j++)
                    if (tx*4+j > ty*4+i) s[i][j] = -1e30f;
        }

        // online softmax update
        #pragma unroll
        for (int i = 0; i < 4; i++) {
            float rm = fmaxf(fmaxf(s[i][0],s[i][1]), fmaxf(s[i][2],s[i][3]));
            #pragma unroll
            for (int off = 8; off; off >>= 1)
                rm = fmaxf(rm, __shfl_xor_sync(0xffffffffu, rm, off));
            float nm = fmaxf(m_i[i], rm);
            float corr = __expf(m_i[i] - nm);
            m_i[i] = nm;
            float rs = 0.0f;
            #pragma unroll
            for (int j = 0; j < 4; j++) {
                float p = __expf(s[i][j] - nm);
                s[i][j] = p; rs += p;
            }
            #pragma unroll
            for (int off = 8; off; off >>= 1)
                rs += __shfl_xor_sync(0xffffffffu, rs, off);
            l_i[i] = l_i[i]*corr + rs;
            o[i][0]*=corr; o[i][1]*=corr; o[i][2]*=corr; o[i][3]*=corr;
        }

        // store P transposed
        #pragma unroll
        for (int i = 0; i < 4; i++)
            #pragma unroll
            for (int j = 0; j < 4; j++)
                ps[(tx*4+j)*68 + ty*4+i] = s[i][j];
        __syncthreads();

        // O += P @ V
        #pragma unroll 4
        for (int kk = 0; kk < 64; kk++) {
            float4 pa = *(const float4*)(ps + kk*68 + ty*4);
            float4 va = *(const float4*)(vs + kk*68 + tx*4);
            float pr[4] = {pa.x,pa.y,pa.z,pa.w};
            float vr[4] = {va.x,va.y,va.z,va.w};
            #pragma unroll
            for (int i = 0; i < 4; i++)
                #pragma unroll
                for (int j = 0; j < 4; j++)
                    o[i][j] += pr[i]*vr[j];
        }
    }

    float* ob = out + (size_t)b*PP*DD + (size_t)h*HDIM;
    #pragma unroll
    for (int i = 0; i < 4; i++) {
        float inv = 1.0f / l_i[i];
        float4 r4;
        r4.x = o[i][0]*inv; r4.y = o[i][1]*inv; r4.z = o[i][2]*inv; r4.w = o[i][3]*inv;
        *(float4*)(ob + (size_t)(q0 + ty*4 + i)*DD + tx*4) = r4;
    }
}

// ---------------- elementwise epilogues ----------------
__global__ void silu_mul_kernel(float* __restrict__ g, const float* __restrict__ u, long n)
{
    long i = (long)blockIdx.x * blockDim.x + threadIdx.x;
    if (i < n) {
        float x = g[i];
        float s = x / (1.0f + __expf(-x));
        g[i] = s * u[i];
    }
}

// eg = silu(eg) * eu * mask[row, col>>8]   (layout [NTOK][E*FE], FE=256)
__global__ void expert_mul_kernel(float* __restrict__ eg, const float* __restrict__ eu,
                                  const float* __restrict__ mask, long n)
{
    long i = (long)blockIdx.x * blockDim.x + threadIdx.x;
    if (i < n) {
        long row = i >> 12;          // /4096
        int  col = (int)(i & 4095);
        int  e   = col >> 8;
        float x = eg[i];
        float s = x / (1.0f + __expf(-x));
        eg[i] = s * eu[i] * mask[row * NE + e];
    }
}

// ---------------- launch ----------------
extern "C" void kernel_launch(void* const* d_in, const int* in_sizes, int n_in,
                              void* d_out, int out_size)
{
    const float* x        = (const float*)d_in[0];
    const float* emask    = (const float*)d_in[1];
    const float* ln1_w    = (const float*)d_in[2];
    const float* wq       = (const float*)d_in[3];
    const float* bq       = (const float*)d_in[4];
    const float* wk       = (const float*)d_in[5];
    const float* bk       = (const float*)d_in[6];
    const float* wv       = (const float*)d_in[7];
    const float* bv       = (const float*)d_in[8];
    const float* wo       = (const float*)d_in[9];
    const float* ln2_w    = (const float*)d_in[10];
    const float* w_gate   = (const float*)d_in[11];
    const float* w_up     = (const float*)d_in[12];
    const float* w_down   = (const float*)d_in[13];
    const float* we_gate  = (const float*)d_in[14];
    const float* we_up    = (const float*)d_in[15];
    const float* we_down  = (const float*)d_in[16];
    float* out = (float*)d_out;

    float *h,*q,*k,*v,*att,*x2,*h2,*gate,*up,*eg,*eu,*tmp;
    cudaGetSymbolAddress((void**)&h,   g_h);
    cudaGetSymbolAddress((void**)&q,   g_q);
    cudaGetSymbolAddress((void**)&k,   g_k);
    cudaGetSymbolAddress((void**)&v,   g_v);
    cudaGetSymbolAddress((void**)&att, g_att);
    cudaGetSymbolAddress((void**)&x2,  g_x2);
    cudaGetSymbolAddress((void**)&h2,  g_h2);
    cudaGetSymbolAddress((void**)&gate,g_gate);
    cudaGetSymbolAddress((void**)&up,  g_up);
    cudaGetSymbolAddress((void**)&eg,  g_eg);
    cudaGetSymbolAddress((void**)&eu,  g_eu);
    cudaGetSymbolAddress((void**)&tmp, g_tmp);

    // 1) h = rmsnorm(x)
    rmsnorm_kernel<<<NTOK, 256>>>(x, ln1_w, h);

    // 2) QKV projections (+bias)
    sgemm_kernel<1><<<dim3(8,64,1), 256>>>(h, wq, q, NTOK, 1024, 1024, 1024, bq, nullptr, 0, 0);
    sgemm_kernel<1><<<dim3(4,64,1), 256>>>(h, wk, k, NTOK,  512, 1024,  512, bk, nullptr, 0, 0);
    sgemm_kernel<1><<<dim3(4,64,1), 256>>>(h, wv, v, NTOK,  512, 1024,  512, bv, nullptr, 0, 0);

    // 3) RoPE on q and k
    {
        long tq = (long)NTOK * HH  * 32;
        rope_kernel<<<(unsigned)((tq + 255) / 256), 256>>>(q, HH, tq);
        long tk = (long)NTOK * KVH * 32;
        rope_kernel<<<(unsigned)((tk + 255) / 256), 256>>>(k, KVH, tk);
    }

    // 4) causal GQA flash attention
    {
        int smem = 4 * 64 * 68 * (int)sizeof(float);
        cudaFuncSetAttribute(flash_kernel, cudaFuncAttributeMaxDynamicSharedMemorySize, smem);
        flash_kernel<<<dim3(PP/64, HH, BB), 256, smem>>>(q, k, v, att);
    }

    // 5) x2 = x + att @ wo
    sgemm_kernel<2><<<dim3(8,64,1), 256>>>(att, wo, x2, NTOK, 1024, 1024, 1024, nullptr, x, 0, 0);

    // 6) h2 = rmsnorm(x2)
    rmsnorm_kernel<<<NTOK, 256>>>(x2, ln2_w, h2);

    // 7) dense MLP
    sgemm_kernel<0><<<dim3(32,64,1), 256>>>(h2, w_gate, gate, NTOK, 4096, 1024, 4096, nullptr, nullptr, 0, 0);
    sgemm_kernel<0><<<dim3(32,64,1), 256>>>(h2, w_up,   up,   NTOK, 4096, 1024, 4096, nullptr, nullptr, 0, 0);
    {
        long n = (long)NTOK * FFN;
        silu_mul_kernel<<<(unsigned)((n + 255) / 256), 256>>>(gate, up, n);
    }
    // tmp = x2 + (silu(g)*u) @ w_down
    sgemm_kernel<2><<<dim3(8,64,1), 256>>>(gate, w_down, tmp, NTOK, 1024, 4096, 1024, nullptr, x2, 0, 0);

    // 8) experts: z-batched gate/up GEMMs into [NTOK][E*FE]
    sgemm_kernel<0><<<dim3(2,64,NE), 256>>>(h2, we_gate, eg, NTOK, 256, 1024, 4096,
                                            nullptr, nullptr, (long)1024*256, 256);
    sgemm_kernel<0><<<dim3(2,64,NE), 256>>>(h2, we_up,   eu, NTOK, 256, 1024, 4096,
                                            nullptr, nullptr, (long)1024*256, 256);
    {
        long n = (long)NTOK * NE * FE;
        expert_mul_kernel<<<(unsigned)((n + 255) / 256), 256>>>(eg, eu, emask, n);
    }
    // 9) out = tmp + (mask-scaled expert acts) @ we_down  (single 8192x4096x1024 GEMM)
    sgemm_kernel<2><<<dim3(8,64,1), 256>>>(eg, we_down, out, NTOK, 1024, 4096, 1024, nullptr, tmp, 0, 0);
}

// round 6
// speedup vs baseline: 1.6266x; 1.6266x over previous
#include <cuda_runtime.h>
#include <cstdint>
#include <math.h>

// ---------------- problem constants ----------------
#define BB   4
#define PP   2048
#define DD   1024
#define HH   16
#define KVH  8
#define HDIM 64
#define FFN  4096
#define NE   16
#define FE   256
#define NTOK (BB*PP)          // 8192

// ---------------- scratch (no allocs allowed) ----------------
__device__ float g_h   [(size_t)NTOK*DD];
__device__ float g_q   [(size_t)NTOK*HH*HDIM];
__device__ float g_k   [(size_t)NTOK*KVH*HDIM];
__device__ float g_v   [(size_t)NTOK*KVH*HDIM];
__device__ float g_att [(size_t)NTOK*DD];
__device__ float g_x2  [(size_t)NTOK*DD];
__device__ float g_h2  [(size_t)NTOK*DD];
__device__ float g_gate[(size_t)NTOK*FFN];
__device__ float g_up  [(size_t)NTOK*FFN];
__device__ float g_eg  [(size_t)NTOK*NE*FE];
__device__ float g_eu  [(size_t)NTOK*NE*FE];
__device__ float g_tmp [(size_t)NTOK*DD];

// =================== tf32 mma.sync GEMM ===================
// C[M x N](+z*sC) = A[M x K] @ (B + z*sB)[K x N]   (lda==K, ldb==N)
// CTA tile 128x128, K staged by 32, double-buffered smem, 8 warps (2x4),
// warp tile 64x32, mma.m16n8k8.tf32. EPI: 0 none, 1 +bias[col], 2 +res.
#define SA 136                        // smem row stride (floats): 128 + 8 pad
#define MG_SMEM (4*32*SA*4)           // 2 bufs * (A+B) * 32*136 floats = 69632 B

__device__ __forceinline__ uint32_t f2tf32(float f) {
    uint32_t u;
    asm("cvt.rna.tf32.f32 %0, %1;" : "=r"(u) : "f"(f));
    return u;
}

__device__ __forceinline__ void mma_tf32(float* d, const uint32_t* a, const uint32_t* b) {
    asm volatile(
        "mma.sync.aligned.m16n8k8.row.col.f32.tf32.tf32.f32 "
        "{%0,%1,%2,%3}, {%4,%5,%6,%7}, {%8,%9}, {%0,%1,%2,%3};"
        : "+f"(d[0]), "+f"(d[1]), "+f"(d[2]), "+f"(d[3])
        : "r"(a[0]), "r"(a[1]), "r"(a[2]), "r"(a[3]), "r"(b[0]), "r"(b[1]));
}

template<int EPI>
__global__ __launch_bounds__(256)
void mgemm_kernel(const float* __restrict__ A, const float* __restrict__ B,
                  float* __restrict__ C, int M, int N, int K, int ldc,
                  const float* __restrict__ bias, const float* __restrict__ res,
                  long sB, long sC)
{
    extern __shared__ __align__(16) float sm[];
    float* As = sm;                 // [2][32][SA]  k-major, m along row
    float* Bs = sm + 2*32*SA;       // [2][32][SA]  k-major, n along row

    B += (long)blockIdx.z * sB;
    C += (long)blockIdx.z * sC;
    const int bm = blockIdx.y * 128, bn = blockIdx.x * 128;
    const int tid  = threadIdx.x;
    const int wid  = tid >> 5, lane = tid & 31;
    const int wm   = (wid & 1) * 64;      // warp M offset
    const int wn   = (wid >> 1) * 32;     // warp N offset
    const int gid  = lane >> 2;           // 0..7
    const int tig  = lane & 3;            // 0..3

    // global load coords (per stage: 4 float4 of A, 4 float4 of B per thread)
    float4 ra[4], rb[4];
    const int am = tid & 127, akg = tid >> 7;      // + it*2 on akg
    const int bn4 = tid & 31, bk = tid >> 5;       // + it*8 on bk

    auto ldg_stage = [&](int t) {
        const int k0 = t * 32;
        #pragma unroll
        for (int it = 0; it < 4; it++) {
            ra[it] = *(const float4*)(A + (size_t)(bm + am) * K + k0 + (akg + it*2) * 4);
            rb[it] = *(const float4*)(B + (size_t)(k0 + bk + it*8) * N + bn + bn4 * 4);
        }
    };
    auto sts_stage = [&](int t) {
        float* as = As + (t & 1) * 32 * SA;
        float* bs = Bs + (t & 1) * 32 * SA;
        #pragma unroll
        for (int it = 0; it < 4; it++) {
            const int kg = akg + it*2;
            float av[4] = {ra[it].x, ra[it].y, ra[it].z, ra[it].w};
            #pragma unroll
            for (int j = 0; j < 4; j++)
                as[(kg*4 + j) * SA + am] = __uint_as_float(f2tf32(av[j]));
            uint32_t b4[4] = {f2tf32(rb[it].x), f2tf32(rb[it].y),
                              f2tf32(rb[it].z), f2tf32(rb[it].w)};
            *(uint4*)(bs + (bk + it*8) * SA + bn4 * 4) =
                make_uint4(b4[0], b4[1], b4[2], b4[3]);
        }
    };

    float acc[4][4][4];
    #pragma unroll
    for (int mt = 0; mt < 4; mt++)
        #pragma unroll
        for (int nt = 0; nt < 4; nt++)
            acc[mt][nt][0]=acc[mt][nt][1]=acc[mt][nt][2]=acc[mt][nt][3]=0.0f;

    const int KT = K / 32;
    ldg_stage(0);
    sts_stage(0);
    __syncthreads();

    for (int t = 0; t < KT; t++) {
        if (t + 1 < KT) ldg_stage(t + 1);
        const float* as = As + (t & 1) * 32 * SA;
        const float* bs = Bs + (t & 1) * 32 * SA;
        #pragma unroll
        for (int kk = 0; kk < 4; kk++) {
            const int kb = kk * 8;
            uint32_t af[4][4], bf[4][2];
            #pragma unroll
            for (int mt = 0; mt < 4; mt++) {
                const int m0 = wm + mt*16;
                af[mt][0] = __float_as_uint(as[(kb + tig    )*SA + m0 + gid    ]);
                af[mt][1] = __float_as_uint(as[(kb + tig    )*SA + m0 + gid + 8]);
                af[mt][2] = __float_as_uint(as[(kb + tig + 4)*SA + m0 + gid    ]);
                af[mt][3] = __float_as_uint(as[(kb + tig + 4)*SA + m0 + gid + 8]);
            }
            #pragma unroll
            for (int nt = 0; nt < 4; nt++) {
                const int n0 = wn + nt*8;
                bf[nt][0] = __float_as_uint(bs[(kb + tig    )*SA + n0 + gid]);
                bf[nt][1] = __float_as_uint(bs[(kb + tig + 4)*SA + n0 + gid]);
            }
            #pragma unroll
            for (int mt = 0; mt < 4; mt++)
                #pragma unroll
                for (int nt = 0; nt < 4; nt++)
                    mma_tf32(acc[mt][nt], af[mt], bf[nt]);
        }
        if (t + 1 < KT) sts_stage(t + 1);
        __syncthreads();
    }

    // epilogue: acc rows = wm+mt*16+gid(+8), cols = wn+nt*8+2*tig(+1)
    #pragma unroll
    for (int mt = 0; mt < 4; mt++) {
        #pragma unroll
        for (int half = 0; half < 2; half++) {
            const int r = bm + wm + mt*16 + gid + half*8;
            #pragma unroll
            for (int nt = 0; nt < 4; nt++) {
                const int c = bn + wn + nt*8 + tig*2;
                float2 o;
                o.x = acc[mt][nt][half*2 + 0];
                o.y = acc[mt][nt][half*2 + 1];
                if (EPI == 1) { o.x += bias[c]; o.y += bias[c+1]; }
                if (EPI == 2) {
                    float2 rv = *(const float2*)(res + (size_t)r * ldc + c);
                    o.x += rv.x; o.y += rv.y;
                }
                *(float2*)(C + (size_t)r * ldc + c) = o;
            }
        }
    }
}

// ---------------- RMSNorm ----------------
__global__ void rmsnorm_kernel(const float* __restrict__ x, const float* __restrict__ w,
                               float* __restrict__ out)
{
    int row = blockIdx.x;
    int tid = threadIdx.x;
    const float4 v = ((const float4*)(x + (size_t)row*DD))[tid];
    float ss = v.x*v.x + v.y*v.y + v.z*v.z + v.w*v.w;
    #pragma unroll
    for (int o = 16; o; o >>= 1) ss += __shfl_xor_sync(0xffffffffu, ss, o);
    __shared__ float red[8];
    if ((tid & 31) == 0) red[tid >> 5] = ss;
    __syncthreads();
    float total = red[0]+red[1]+red[2]+red[3]+red[4]+red[5]+red[6]+red[7];
    float sc = rsqrtf(total * (1.0f/DD) + 1e-6f);
    const float4 wv = ((const float4*)w)[tid];
    float4 o4;
    o4.x = v.x*sc*wv.x; o4.y = v.y*sc*wv.y; o4.z = v.z*sc*wv.z; o4.w = v.w*sc*wv.w;
    ((float4*)(out + (size_t)row*DD))[tid] = o4;
}

// ---------------- RoPE ----------------
__global__ void rope_kernel(float* __restrict__ buf, int nheads, long total)
{
    long idx = (long)blockIdx.x * blockDim.x + threadIdx.x;
    if (idx >= total) return;
    int  i    = (int)(idx & 31);
    int  head = (int)((idx >> 5) % nheads);
    long t    = idx / (32L * nheads);
    int  p    = (int)(t % PP);
    float inv = powf(10000.0f, -(float)i * (1.0f/32.0f));
    float ang = (float)p * inv;
    float c = cosf(ang), s = sinf(ang);
    float* v = buf + t * ((size_t)nheads * HDIM) + (size_t)head * HDIM + i;
    float a = v[0], b = v[32];
    v[0]  = a*c - b*s;
    v[32] = b*c + a*s;
}

// ---------------- causal flash attention (fp32) ----------------
__global__ __launch_bounds__(256, 2)
void flash_kernel(const float* __restrict__ q, const float* __restrict__ k,
                  const float* __restrict__ v, float* __restrict__ out)
{
    extern __shared__ float sm[];
    float* qs = sm;
    float* ks = sm + 64*68;
    float* vs = sm + 2*64*68;
    float* ps = sm + 3*64*68;

    const int b = blockIdx.z, h = blockIdx.y, qt = blockIdx.x;
    const int q0 = qt * 64;
    const float* qb = q + (size_t)b*PP*(HH*HDIM)  + (size_t)h*HDIM;
    const float* kb = k + (size_t)b*PP*(KVH*HDIM) + (size_t)(h>>1)*HDIM;
    const float* vb = v + (size_t)b*PP*(KVH*HDIM) + (size_t)(h>>1)*HDIM;

    const int tid = threadIdx.x;
    const int tx = tid & 15, ty = tid >> 4;
    const int lr = tid >> 4, lc = (tid & 15) * 4;

    for (int rr = lr; rr < 64; rr += 16) {
        float4 a = *(const float4*)(qb + (size_t)(q0+rr)*(HH*HDIM) + lc);
        qs[(lc+0)*68+rr] = a.x*0.125f; qs[(lc+1)*68+rr] = a.y*0.125f;
        qs[(lc+2)*68+rr] = a.z*0.125f; qs[(lc+3)*68+rr] = a.w*0.125f;
    }

    float m_i[4], l_i[4], o[4][4];
    #pragma unroll
    for (int i = 0; i < 4; i++) {
        m_i[i] = -1e30f; l_i[i] = 0.0f;
        o[i][0]=o[i][1]=o[i][2]=o[i][3]=0.0f;
    }

    for (int t = 0; t <= qt; t++) {
        const int k0 = t * 64;
        __syncthreads();
        for (int rr = lr; rr < 64; rr += 16) {
            float4 a = *(const float4*)(kb + (size_t)(k0+rr)*(KVH*HDIM) + lc);
            ks[(lc+0)*68+rr] = a.x; ks[(lc+1)*68+rr] = a.y;
            ks[(lc+2)*68+rr] = a.z; ks[(lc+3)*68+rr] = a.w;
            float4 w4 = *(const float4*)(vb + (size_t)(k0+rr)*(KVH*HDIM) + lc);
            *(float4*)(vs + rr*68 + lc) = w4;
        }
        __syncthreads();

        float s[4][4] = {{0,0,0,0},{0,0,0,0},{0,0,0,0},{0,0,0,0}};
        #pragma unroll 4
        for (int kk = 0; kk < 64; kk++) {
            float4 qa = *(const float4*)(qs + kk*68 + ty*4);
            float4 ka = *(const float4*)(ks + kk*68 + tx*4);
            float qr[4] = {qa.x,qa.y,qa.z,qa.w};
            float kr[4] = {ka.x,ka.y,ka.z,ka.w};
            #pragma unroll
            for (int i = 0; i < 4; i++)
                #pragma unroll
                for (int j = 0; j < 4; j++)
                    s[i][j] += qr[i]*kr[j];
        }

        if (t == qt) {
            #pragma unroll
            for (int i = 0; i < 4; i++)
                #pragma unroll
                for (int j = 0; j < 4; j++)
                    if (tx*4+j > ty*4+i) s[i][j] = -1e30f;
        }

        #pragma unroll
        for (int i = 0; i < 4; i++) {
            float rm = fmaxf(fmaxf(s[i][0],s[i][1]), fmaxf(s[i][2],s[i][3]));
            #pragma unroll
            for (int off = 8; off; off >>= 1)
                rm = fmaxf(rm, __shfl_xor_sync(0xffffffffu, rm, off));
            float nm = fmaxf(m_i[i], rm);
            float corr = __expf(m_i[i] - nm);
            m_i[i] = nm;
            float rs = 0.0f;
            #pragma unroll
            for (int j = 0; j < 4; j++) {
                float p = __expf(s[i][j] - nm);
                s[i][j] = p; rs += p;
            }
            #pragma unroll
            for (int off = 8; off; off >>= 1)
                rs += __shfl_xor_sync(0xffffffffu, rs, off);
            l_i[i] = l_i[i]*corr + rs;
            o[i][0]*=corr; o[i][1]*=corr; o[i][2]*=corr; o[i][3]*=corr;
        }

        #pragma unroll
        for (int i = 0; i < 4; i++)
            #pragma unroll
            for (int j = 0; j < 4; j++)
                ps[(tx*4+j)*68 + ty*4+i] = s[i][j];
        __syncthreads();

        #pragma unroll 4
        for (int kk = 0; kk < 64; kk++) {
            float4 pa = *(const float4*)(ps + kk*68 + ty*4);
            float4 va = *(const float4*)(vs + kk*68 + tx*4);
            float pr[4] = {pa.x,pa.y,pa.z,pa.w};
            float vr[4] = {va.x,va.y,va.z,va.w};
            #pragma unroll
            for (int i = 0; i < 4; i++)
                #pragma unroll
                for (int j = 0; j < 4; j++)
                    o[i][j] += pr[i]*vr[j];
        }
    }

    float* ob = out + (size_t)b*PP*DD + (size_t)h*HDIM;
    #pragma unroll
    for (int i = 0; i < 4; i++) {
        float inv = 1.0f / l_i[i];
        float4 r4;
        r4.x = o[i][0]*inv; r4.y = o[i][1]*inv; r4.z = o[i][2]*inv; r4.w = o[i][3]*inv;
        *(float4*)(ob + (size_t)(q0 + ty*4 + i)*DD + tx*4) = r4;
    }
}

// ---------------- elementwise epilogues ----------------
__global__ void silu_mul_kernel(float* __restrict__ g, const float* __restrict__ u, long n)
{
    long i = (long)blockIdx.x * blockDim.x + threadIdx.x;
    if (i < n) {
        float x = g[i];
        float s = x / (1.0f + __expf(-x));
        g[i] = s * u[i];
    }
}

__global__ void expert_mul_kernel(float* __restrict__ eg, const float* __restrict__ eu,
                                  const float* __restrict__ mask, long n)
{
    long i = (long)blockIdx.x * blockDim.x + threadIdx.x;
    if (i < n) {
        long row = i >> 12;
        int  col = (int)(i & 4095);
        int  e   = col >> 8;
        float x = eg[i];
        float s = x / (1.0f + __expf(-x));
        eg[i] = s * eu[i] * mask[row * NE + e];
    }
}

// ---------------- launch ----------------
extern "C" void kernel_launch(void* const* d_in, const int* in_sizes, int n_in,
                              void* d_out, int out_size)
{
    const float* x        = (const float*)d_in[0];
    const float* emask    = (const float*)d_in[1];
    const float* ln1_w    = (const float*)d_in[2];
    const float* wq       = (const float*)d_in[3];
    const float* bq       = (const float*)d_in[4];
    const float* wk       = (const float*)d_in[5];
    const float* bk       = (const float*)d_in[6];
    const float* wv       = (const float*)d_in[7];
    const float* bv       = (const float*)d_in[8];
    const float* wo       = (const float*)d_in[9];
    const float* ln2_w    = (const float*)d_in[10];
    const float* w_gate   = (const float*)d_in[11];
    const float* w_up     = (const float*)d_in[12];
    const float* w_down   = (const float*)d_in[13];
    const float* we_gate  = (const float*)d_in[14];
    const float* we_up    = (const float*)d_in[15];
    const float* we_down  = (const float*)d_in[16];
    float* out = (float*)d_out;

    float *h,*q,*k,*v,*att,*x2,*h2,*gate,*up,*eg,*eu,*tmp;
    cudaGetSymbolAddress((void**)&h,   g_h);
    cudaGetSymbolAddress((void**)&q,   g_q);
    cudaGetSymbolAddress((void**)&k,   g_k);
    cudaGetSymbolAddress((void**)&v,   g_v);
    cudaGetSymbolAddress((void**)&att, g_att);
    cudaGetSymbolAddress((void**)&x2,  g_x2);
    cudaGetSymbolAddress((void**)&h2,  g_h2);
    cudaGetSymbolAddress((void**)&gate,g_gate);
    cudaGetSymbolAddress((void**)&up,  g_up);
    cudaGetSymbolAddress((void**)&eg,  g_eg);
    cudaGetSymbolAddress((void**)&eu,  g_eu);
    cudaGetSymbolAddress((void**)&tmp, g_tmp);

    cudaFuncSetAttribute(mgemm_kernel<0>, cudaFuncAttributeMaxDynamicSharedMemorySize, MG_SMEM);
    cudaFuncSetAttribute(mgemm_kernel<1>, cudaFuncAttributeMaxDynamicSharedMemorySize, MG_SMEM);
    cudaFuncSetAttribute(mgemm_kernel<2>, cudaFuncAttributeMaxDynamicSharedMemorySize, MG_SMEM);

    // 1) h = rmsnorm(x)
    rmsnorm_kernel<<<NTOK, 256>>>(x, ln1_w, h);

    // 2) QKV projections (+bias)
    mgemm_kernel<1><<<dim3(8,64,1), 256, MG_SMEM>>>(h, wq, q, NTOK, 1024, 1024, 1024, bq, nullptr, 0, 0);
    mgemm_kernel<1><<<dim3(4,64,1), 256, MG_SMEM>>>(h, wk, k, NTOK,  512, 1024,  512, bk, nullptr, 0, 0);
    mgemm_kernel<1><<<dim3(4,64,1), 256, MG_SMEM>>>(h, wv, v, NTOK,  512, 1024,  512, bv, nullptr, 0, 0);

    // 3) RoPE
    {
        long tq = (long)NTOK * HH  * 32;
        rope_kernel<<<(unsigned)((tq + 255) / 256), 256>>>(q, HH, tq);
        long tk = (long)NTOK * KVH * 32;
        rope_kernel<<<(unsigned)((tk + 255) / 256), 256>>>(k, KVH, tk);
    }

    // 4) attention
    {
        int smem = 4 * 64 * 68 * (int)sizeof(float);
        cudaFuncSetAttribute(flash_kernel, cudaFuncAttributeMaxDynamicSharedMemorySize, smem);
        flash_kernel<<<dim3(PP/64, HH, BB), 256, smem>>>(q, k, v, att);
    }

    // 5) x2 = x + att @ wo
    mgemm_kernel<2><<<dim3(8,64,1), 256, MG_SMEM>>>(att, wo, x2, NTOK, 1024, 1024, 1024, nullptr, x, 0, 0);

    // 6) h2 = rmsnorm(x2)
    rmsnorm_kernel<<<NTOK, 256>>>(x2, ln2_w, h2);

    // 7) dense MLP
    mgemm_kernel<0><<<dim3(32,64,1), 256, MG_SMEM>>>(h2, w_gate, gate, NTOK, 4096, 1024, 4096, nullptr, nullptr, 0, 0);
    mgemm_kernel<0><<<dim3(32,64,1), 256, MG_SMEM>>>(h2, w_up,   up,   NTOK, 4096, 1024, 4096, nullptr, nullptr, 0, 0);
    {
        long n = (long)NTOK * FFN;
        silu_mul_kernel<<<(unsigned)((n + 255) / 256), 256>>>(gate, up, n);
    }
    mgemm_kernel<2><<<dim3(8,64,1), 256, MG_SMEM>>>(gate, w_down, tmp, NTOK, 1024, 4096, 1024, nullptr, x2, 0, 0);

    // 8) experts (z-batched)
    mgemm_kernel<0><<<dim3(2,64,NE), 256, MG_SMEM>>>(h2, we_gate, eg, NTOK, 256, 1024, 4096,
                                                     nullptr, nullptr, (long)1024*256, 256);
    mgemm_kernel<0><<<dim3(2,64,NE), 256, MG_SMEM>>>(h2, we_up,   eu, NTOK, 256, 1024, 4096,
                                                     nullptr, nullptr, (long)1024*256, 256);
    {
        long n = (long)NTOK * NE * FE;
        expert_mul_kernel<<<(unsigned)((n + 255) / 256), 256>>>(eg, eu, emask, n);
    }
    // 9) out = tmp + expert_acts @ we_down
    mgemm_kernel<2><<<dim3(8,64,1), 256, MG_SMEM>>>(eg, we_down, out, NTOK, 1024, 4096, 1024, nullptr, tmp, 0, 0);
}